// round 2
// baseline (speedup 1.0000x reference)
#include <cuda_runtime.h>
#include <cuda_bf16.h>
#include <cstdint>

#define NB 512
#define ND 512
#define MARGIN 0.2f
#define INF_F 1e30f

typedef unsigned long long ull;

// ---------------- scratch (no allocations allowed) ----------------
__device__ float g_P[2][NB * NB];   // split-K partial dot products (2 MB)
__device__ float g_sq[NB];          // row squared norms

struct Ctl {
    unsigned long long acc;   // fixed-point loss sum (x 2^32)
    unsigned long long cnt;   // valid pair count
    int ready[8];             // per 64-row band: tiles finished (16 = done)
    int sqdone;               // 8 = all norms written
    int done;                 // mining blocks finished (32 = all)
    int pad;
};
__device__ Ctl g_ctl;

// ---------------- f32x2 packed helpers ----------------
__device__ __forceinline__ ull dup2(float x) {
    ull r;
    asm("mov.b64 %0, {%1, %1};" : "=l"(r) : "r"(__float_as_uint(x)));
    return r;
}
__device__ __forceinline__ void fma2(ull& d, ull a, ull b) {
    asm("fma.rn.f32x2 %0, %1, %2, %0;" : "+l"(d) : "l"(a), "l"(b));
}
__device__ __forceinline__ void unpk(ull v, float& lo, float& hi) {
    unsigned l, h;
    asm("mov.b64 {%0, %1}, %2;" : "=r"(l), "=r"(h) : "l"(v));
    lo = __uint_as_float(l);
    hi = __uint_as_float(h);
}

// =====================================================================
// Single fused kernel. grid (8, 8, 2), 128 threads.
//  bx: 64-col tile, by: 64-row band, bz: K-split half (256 dims each).
//  Phase 0 (diag blocks, bz=0): row norms for the band.
//  Phase 1 (all): 64x64x256 partial SGEMM -> g_P[bz].
//  Phase 2 (last 4 finishers of each band): semi-hard mining for 16 anchors.
//  Phase 3 (last mining block): finalize scalar.
// =====================================================================
__global__ void __launch_bounds__(128, 1)
k_main(const float* __restrict__ E, const int* __restrict__ labels,
       float* __restrict__ out) {
    __shared__ float As[32][64];   // [k][row]
    __shared__ float Bs[32][64];   // [k][col]
    __shared__ int s_old;

    const int tid = threadIdx.x;
    const int bx = blockIdx.x, by = blockIdx.y, bz = blockIdx.z;
    const int lane = tid & 31, warp = tid >> 5;

    // ---------- phase 0: row norms (one diagonal block per band) ----------
    if (bx == by && bz == 0) {
        for (int r = warp; r < 64; r += 4) {
            const float* row = E + (size_t)(by * 64 + r) * ND;
            float s = 0.f;
#pragma unroll
            for (int k = lane; k < ND; k += 32) { float v = row[k]; s += v * v; }
#pragma unroll
            for (int o = 16; o > 0; o >>= 1)
                s += __shfl_xor_sync(0xFFFFFFFFu, s, o);
            if (lane == 0) g_sq[by * 64 + r] = s;
        }
        __threadfence();
        __syncthreads();
        if (tid == 0) atomicAdd(&g_ctl.sqdone, 1);
    }

    // ---------- phase 1: partial GEMM ----------
    const float* Ag = E + (size_t)by * 64 * ND + bz * 256;
    const float* Bg = E + (size_t)bx * 64 * ND + bz * 256;

    const int tx = tid & 15;   // 4 cols each
    const int ty = tid >> 4;   // 8 rows each (as 4 row-pairs)

    ull acc[4][4];
#pragma unroll
    for (int i = 0; i < 4; i++)
#pragma unroll
        for (int j = 0; j < 4; j++) acc[i][j] = 0ull;

    float4 pa[4], pb[4];
    // prefetch k-tile 0
#pragma unroll
    for (int q = 0; q < 4; q++) {
        int idx = q * 128 + tid;
        int row = idx >> 3, kg = idx & 7;
        pa[q] = *reinterpret_cast<const float4*>(Ag + (size_t)row * ND + kg * 4);
        pb[q] = *reinterpret_cast<const float4*>(Bg + (size_t)row * ND + kg * 4);
    }

    for (int s = 0; s < 8; s++) {
        // store staged regs to transposed smem
#pragma unroll
        for (int q = 0; q < 4; q++) {
            int idx = q * 128 + tid;
            int row = idx >> 3, kg = idx & 7;
            As[kg * 4 + 0][row] = pa[q].x; As[kg * 4 + 1][row] = pa[q].y;
            As[kg * 4 + 2][row] = pa[q].z; As[kg * 4 + 3][row] = pa[q].w;
            Bs[kg * 4 + 0][row] = pb[q].x; Bs[kg * 4 + 1][row] = pb[q].y;
            Bs[kg * 4 + 2][row] = pb[q].z; Bs[kg * 4 + 3][row] = pb[q].w;
        }
        __syncthreads();

        if (s < 7) {
            const float* An = Ag + (s + 1) * 32;
            const float* Bn = Bg + (s + 1) * 32;
#pragma unroll
            for (int q = 0; q < 4; q++) {
                int idx = q * 128 + tid;
                int row = idx >> 3, kg = idx & 7;
                pa[q] = *reinterpret_cast<const float4*>(An + (size_t)row * ND + kg * 4);
                pb[q] = *reinterpret_cast<const float4*>(Bn + (size_t)row * ND + kg * 4);
            }
        }

#pragma unroll
        for (int kk = 0; kk < 32; kk++) {
            // 4 row-pairs as native 8B LDS
            ull ap0 = *reinterpret_cast<const ull*>(&As[kk][ty * 8 + 0]);
            ull ap1 = *reinterpret_cast<const ull*>(&As[kk][ty * 8 + 2]);
            ull ap2 = *reinterpret_cast<const ull*>(&As[kk][ty * 8 + 4]);
            ull ap3 = *reinterpret_cast<const ull*>(&As[kk][ty * 8 + 6]);
            float4 bv = *reinterpret_cast<const float4*>(&Bs[kk][tx * 4]);
            ull b0 = dup2(bv.x), b1 = dup2(bv.y), b2 = dup2(bv.z), b3 = dup2(bv.w);
            fma2(acc[0][0], ap0, b0); fma2(acc[0][1], ap0, b1);
            fma2(acc[0][2], ap0, b2); fma2(acc[0][3], ap0, b3);
            fma2(acc[1][0], ap1, b0); fma2(acc[1][1], ap1, b1);
            fma2(acc[1][2], ap1, b2); fma2(acc[1][3], ap1, b3);
            fma2(acc[2][0], ap2, b0); fma2(acc[2][1], ap2, b1);
            fma2(acc[2][2], ap2, b2); fma2(acc[2][3], ap2, b3);
            fma2(acc[3][0], ap3, b0); fma2(acc[3][1], ap3, b1);
            fma2(acc[3][2], ap3, b2); fma2(acc[3][3], ap3, b3);
        }
        __syncthreads();
    }

    // epilogue: store raw partial dot products
    {
        float* dst = g_P[bz];
        const int c = bx * 64 + tx * 4;
#pragma unroll
        for (int ip = 0; ip < 4; ip++) {
            float lo0, hi0, lo1, hi1, lo2, hi2, lo3, hi3;
            unpk(acc[ip][0], lo0, hi0); unpk(acc[ip][1], lo1, hi1);
            unpk(acc[ip][2], lo2, hi2); unpk(acc[ip][3], lo3, hi3);
            int r0 = by * 64 + ty * 8 + 2 * ip;
            *reinterpret_cast<float4*>(&dst[(size_t)r0 * NB + c]) =
                make_float4(lo0, lo1, lo2, lo3);
            *reinterpret_cast<float4*>(&dst[(size_t)(r0 + 1) * NB + c]) =
                make_float4(hi0, hi1, hi2, hi3);
        }
    }

    // ---------- band readiness ----------
    __threadfence();
    __syncthreads();
    if (tid == 0) s_old = atomicAdd(&g_ctl.ready[by], 1);
    __syncthreads();
    const int old = s_old;
    if (old < 12) return;              // only last 4 finishers mine
    const int slice = old - 12;        // 0..3 -> 16 anchors each

    // wait for full band + all norms (all 128 blocks are wave-1 resident
    // on >=148 SMs, so producers are guaranteed to run)
    if (tid == 0) {
        while (*(volatile int*)&g_ctl.ready[by] < 16) {}
        while (*(volatile int*)&g_ctl.sqdone < 8) {}
    }
    __syncthreads();
    __threadfence();

    // ---------- phase 2: semi-hard mining (warp per anchor, 4 each) ----------
    float* s_sq = &As[0][0];           // reuse smem: 512 floats
    int* s_lab = (int*)&Bs[0][0];      // 512 ints
    for (int i = tid; i < NB; i += 128) {
        s_sq[i] = g_sq[i];
        s_lab[i] = labels[i];
    }
    __syncthreads();

    long long accll = 0, cntll = 0;    // per-warp (lane 0 holds result)
    for (int ai = 0; ai < 4; ai++) {
        const int a = by * 64 + slice * 16 + warp * 4 + ai;
        const float sqa = s_sq[a];
        const int la = s_lab[a];

        float d[16];
        int lb[16];
#pragma unroll
        for (int t = 0; t < 16; t++) {
            int j = t * 32 + lane;
            float p = g_P[0][(size_t)a * NB + j] + g_P[1][(size_t)a * NB + j];
            d[t] = fmaxf(sqa + s_sq[j] - 2.f * p, 0.f);
            lb[t] = s_lab[j];
        }

        float nmin = INF_F;
#pragma unroll
        for (int t = 0; t < 16; t++)
            if (lb[t] != la) nmin = fminf(nmin, d[t]);
#pragma unroll
        for (int o = 16; o > 0; o >>= 1)
            nmin = fminf(nmin, __shfl_xor_sync(0xFFFFFFFFu, nmin, o));

        float sum = 0.f;
        int cnt = 0;
        if (nmin < 1e29f) {
#pragma unroll 1
            for (int t = 0; t < 16; t++) {
                int j = t * 32 + lane;
                unsigned m = __ballot_sync(0xFFFFFFFFu, (j > a) && (lb[t] == la));
                while (m) {
                    int lp = __ffs(m) - 1;
                    m &= m - 1;
                    float ap = __shfl_sync(0xFFFFFFFFu, d[t], lp);
                    float apM = ap + MARGIN;
                    float smin = INF_F;
#pragma unroll
                    for (int tt = 0; tt < 16; tt++) {
                        bool semi = (lb[tt] != la) && (d[tt] > ap) && (d[tt] < apM);
                        if (semi) smin = fminf(smin, d[tt]);
                    }
#pragma unroll
                    for (int o = 16; o > 0; o >>= 1)
                        smin = fminf(smin, __shfl_xor_sync(0xFFFFFFFFu, smin, o));
                    float negd = (smin < 1e29f) ? smin : nmin;
                    sum += fmaxf(ap - negd + MARGIN, 0.f);
                    cnt++;
                }
            }
        }
        if (lane == 0) {
            accll += __double2ll_rn((double)sum * 4294967296.0);
            cntll += cnt;
        }
    }
    if (lane == 0) {
        atomicAdd(&g_ctl.acc, (ull)accll);
        atomicAdd(&g_ctl.cnt, (ull)cntll);
    }

    // ---------- phase 3: finalize ----------
    __syncthreads();
    __threadfence();
    if (tid == 0) {
        int o = atomicAdd(&g_ctl.done, 1);
        if (o == 31) {
            __threadfence();
            ull a = *(volatile ull*)&g_ctl.acc;
            ull c = *(volatile ull*)&g_ctl.cnt;
            double loss = ((double)a / 4294967296.0) /
                          (double)(c ? c : 1ull);
            out[0] = (float)loss;
        }
    }
}

extern "C" void kernel_launch(void* const* d_in, const int* in_sizes, int n_in,
                              void* d_out, int out_size) {
    const float* emb = (const float*)d_in[0];
    const int* labels = (const int*)d_in[1];
    float* out = (float*)d_out;

    void* ctl = nullptr;
    cudaGetSymbolAddress(&ctl, g_ctl);
    cudaMemsetAsync(ctl, 0, sizeof(Ctl));

    dim3 grid(8, 8, 2);
    k_main<<<grid, 128>>>(emb, labels, out);
}

// round 3
// speedup vs baseline: 1.0181x; 1.0181x over previous
#include <cuda_runtime.h>
#include <cuda_bf16.h>
#include <cstdint>

#define NB 512
#define ND 512
#define MARGIN 0.2f
#define INF_F 1e30f
#define NSPLIT 8        // K splits of 64
#define KB 64           // K per block

typedef unsigned long long ull;

// ---------------- scratch ----------------
__device__ float g_P[NSPLIT][NB * NB];   // split-K partial dot products (8 MB)

struct Ctl {
    unsigned long long acc;   // fixed-point loss sum (x 2^32)
    unsigned long long cnt;   // valid pair count
    int ready[4];             // per 128-row band: finished blocks (32 = done)
    int diagdone;             // 32 = all diagonal tiles done
    int done;                 // mining blocks finished (64 = all)
};
__device__ Ctl g_ctl;

// ---------------- f32x2 helpers ----------------
__device__ __forceinline__ ull dup2(float x) {
    ull r;
    asm("mov.b64 %0, {%1, %1};" : "=l"(r) : "r"(__float_as_uint(x)));
    return r;
}
__device__ __forceinline__ void fma2(ull& d, ull a, ull b) {
    asm("fma.rn.f32x2 %0, %1, %2, %0;" : "+l"(d) : "l"(a), "l"(b));
}
__device__ __forceinline__ void unpk(ull v, float& lo, float& hi) {
    unsigned l, h;
    asm("mov.b64 {%0, %1}, %2;" : "=r"(l), "=r"(h) : "l"(v));
    lo = __uint_as_float(l);
    hi = __uint_as_float(h);
}

// =====================================================================
// Fused kernel. grid (4,4,8), 256 threads.
//   bx=bj col tile, by=bi row band (128 rows), bz = K split (64 dims).
//   GEMM: 128x128x64 partial -> g_P[bz]. Then last-16 finishers of each
//   band mine 8 anchors each (warp per anchor). sq comes from GEMM diag.
// =====================================================================
__global__ void __launch_bounds__(256, 1)
k_main(const float* __restrict__ E, const int* __restrict__ labels,
       float* __restrict__ out) {
    extern __shared__ float smem[];
    float (*As)[128] = reinterpret_cast<float(*)[128]>(smem);          // 32 KB
    ull   (*Bs)[128] = reinterpret_cast<ull(*)[128]>(smem + KB * 128); // 64 KB (dup'd)
    __shared__ int s_old;

    const int tid = threadIdx.x;
    const int bj = blockIdx.x, bi = blockIdx.y, bz = blockIdx.z;
    const int lane = tid & 31, warp = tid >> 5;

    // ---------- stage tiles: A[k][row] transposed, B[k][col] duplicated ----------
    {
        const int r = tid & 127;
        const int half = tid >> 7;                  // 0/1 -> k halves
        const float* Ag = E + (size_t)(bi * 128 + r) * ND + bz * KB;
        const float* Bg = E + (size_t)(bj * 128 + r) * ND + bz * KB;
#pragma unroll
        for (int i = 0; i < 8; i++) {
            const int k = half * 32 + i * 4;
            float4 va = *reinterpret_cast<const float4*>(Ag + k);
            float4 vb = *reinterpret_cast<const float4*>(Bg + k);
            As[k + 0][r] = va.x; As[k + 1][r] = va.y;
            As[k + 2][r] = va.z; As[k + 3][r] = va.w;
            Bs[k + 0][r] = dup2(vb.x); Bs[k + 1][r] = dup2(vb.y);
            Bs[k + 2][r] = dup2(vb.z); Bs[k + 3][r] = dup2(vb.w);
        }
    }
    __syncthreads();

    // ---------- compute: 8x8 per thread as 4 row-pairs x 8 cols ----------
    const int tx = tid & 15;          // col group  -> cols tx*8..+7
    const int ty = tid >> 4;          // row group  -> rows ty*8..+7

    ull acc[4][8];
#pragma unroll
    for (int i = 0; i < 4; i++)
#pragma unroll
        for (int j = 0; j < 8; j++) acc[i][j] = 0ull;

#pragma unroll 8
    for (int kk = 0; kk < KB; kk++) {
        ull a0 = *reinterpret_cast<const ull*>(&As[kk][ty * 8 + 0]);
        ull a1 = *reinterpret_cast<const ull*>(&As[kk][ty * 8 + 2]);
        ull a2 = *reinterpret_cast<const ull*>(&As[kk][ty * 8 + 4]);
        ull a3 = *reinterpret_cast<const ull*>(&As[kk][ty * 8 + 6]);
        ull b[8];
#pragma unroll
        for (int j = 0; j < 8; j++) b[j] = Bs[kk][tx * 8 + j];
#pragma unroll
        for (int j = 0; j < 8; j++) {
            fma2(acc[0][j], a0, b[j]);
            fma2(acc[1][j], a1, b[j]);
            fma2(acc[2][j], a2, b[j]);
            fma2(acc[3][j], a3, b[j]);
        }
    }

    // ---------- epilogue: store partial tile ----------
    {
        float* dst = g_P[bz];
        const int c = bj * 128 + tx * 8;
#pragma unroll
        for (int rp = 0; rp < 4; rp++) {
            float lo[8], hi[8];
#pragma unroll
            for (int j = 0; j < 8; j++) unpk(acc[rp][j], lo[j], hi[j]);
            const int r0 = bi * 128 + ty * 8 + 2 * rp;
            float4* p0 = reinterpret_cast<float4*>(&dst[(size_t)r0 * NB + c]);
            float4* p1 = reinterpret_cast<float4*>(&dst[(size_t)(r0 + 1) * NB + c]);
            p0[0] = make_float4(lo[0], lo[1], lo[2], lo[3]);
            p0[1] = make_float4(lo[4], lo[5], lo[6], lo[7]);
            p1[0] = make_float4(hi[0], hi[1], hi[2], hi[3]);
            p1[1] = make_float4(hi[4], hi[5], hi[6], hi[7]);
        }
    }

    __threadfence();
    __syncthreads();
    if (tid == 0) {
        if (bi == bj) atomicAdd(&g_ctl.diagdone, 1);
        s_old = atomicAdd(&g_ctl.ready[bi], 1);
    }
    __syncthreads();
    const int old = s_old;
    if (old < 16) return;              // only last 16 finishers per band mine
    const int slice = old - 16;        // 0..15 -> 8 anchors each

    // wait for full band + all diagonal tiles (all 128 blocks wave-1 resident)
    if (tid == 0) {
        while (*(volatile int*)&g_ctl.ready[bi] < 32 ||
               *(volatile int*)&g_ctl.diagdone < 32) {}
    }
    __syncthreads();
    __threadfence();

    // ---------- mining setup: sq from GEMM diagonal, labels -> smem ----------
    float* s_sq = smem;                    // 512 floats
    int* s_lab = reinterpret_cast<int*>(smem + NB);
    for (int j = tid; j < NB; j += 256) {
        float s = 0.f;
#pragma unroll
        for (int z = 0; z < NSPLIT; z++) s += g_P[z][(size_t)j * NB + j];
        s_sq[j] = s;
        s_lab[j] = labels[j];
    }
    __syncthreads();

    // ---------- mining: warp per anchor, 1 anchor per warp per slice ----------
    // anchors: a = bi*128 + slice*8 + warp
    long long accll = 0, cntll = 0;
    {
        const int a = bi * 128 + slice * 8 + warp;
        const float sqa = s_sq[a];
        const int la = s_lab[a];

        // j mapping: reg idx = g*4+e  ->  j = g*128 + lane*4 + e
        float d[16];
        int lb[16];
#pragma unroll
        for (int g = 0; g < 4; g++) {
            const int j0 = g * 128 + lane * 4;
            float4 p = make_float4(0.f, 0.f, 0.f, 0.f);
#pragma unroll
            for (int z = 0; z < NSPLIT; z++) {
                float4 v = *reinterpret_cast<const float4*>(&g_P[z][(size_t)a * NB + j0]);
                p.x += v.x; p.y += v.y; p.z += v.z; p.w += v.w;
            }
            float4 sq4 = *reinterpret_cast<const float4*>(&s_sq[j0]);
            int4 lb4 = *reinterpret_cast<const int4*>(&s_lab[j0]);
            d[g * 4 + 0] = fmaxf(sqa + sq4.x - 2.f * p.x, 0.f);
            d[g * 4 + 1] = fmaxf(sqa + sq4.y - 2.f * p.y, 0.f);
            d[g * 4 + 2] = fmaxf(sqa + sq4.z - 2.f * p.z, 0.f);
            d[g * 4 + 3] = fmaxf(sqa + sq4.w - 2.f * p.w, 0.f);
            lb[g * 4 + 0] = lb4.x; lb[g * 4 + 1] = lb4.y;
            lb[g * 4 + 2] = lb4.z; lb[g * 4 + 3] = lb4.w;
        }

        float nmin = INF_F;
#pragma unroll
        for (int t = 0; t < 16; t++)
            if (lb[t] != la) nmin = fminf(nmin, d[t]);
#pragma unroll
        for (int o = 16; o > 0; o >>= 1)
            nmin = fminf(nmin, __shfl_xor_sync(0xFFFFFFFFu, nmin, o));

        float sum = 0.f;
        int cnt = 0;
        if (nmin < 1e29f) {
#pragma unroll 1
            for (int t = 0; t < 16; t++) {
                const int j = (t >> 2) * 128 + lane * 4 + (t & 3);
                unsigned m = __ballot_sync(0xFFFFFFFFu, (j > a) && (lb[t] == la));
                while (m) {
                    const int lp = __ffs(m) - 1;
                    m &= m - 1;
                    const float ap = __shfl_sync(0xFFFFFFFFu, d[t], lp);
                    const float apM = ap + MARGIN;
                    float smin = INF_F;
#pragma unroll
                    for (int tt = 0; tt < 16; tt++) {
                        bool semi = (lb[tt] != la) && (d[tt] > ap) && (d[tt] < apM);
                        if (semi) smin = fminf(smin, d[tt]);
                    }
#pragma unroll
                    for (int o = 16; o > 0; o >>= 1)
                        smin = fminf(smin, __shfl_xor_sync(0xFFFFFFFFu, smin, o));
                    const float negd = (smin < 1e29f) ? smin : nmin;
                    sum += fmaxf(ap - negd + MARGIN, 0.f);
                    cnt++;
                }
            }
        }
        if (lane == 0) {
            accll += __double2ll_rn((double)sum * 4294967296.0);
            cntll += cnt;
        }
    }
    if (lane == 0 && (accll | cntll)) {
        atomicAdd(&g_ctl.acc, (ull)accll);
        atomicAdd(&g_ctl.cnt, (ull)cntll);
    }

    // ---------- finalize ----------
    __syncthreads();
    __threadfence();
    if (tid == 0) {
        const int o = atomicAdd(&g_ctl.done, 1);
        if (o == 63) {
            __threadfence();
            ull a = *(volatile ull*)&g_ctl.acc;
            ull c = *(volatile ull*)&g_ctl.cnt;
            out[0] = (float)(((double)a / 4294967296.0) / (double)(c ? c : 1ull));
        }
    }
}

extern "C" void kernel_launch(void* const* d_in, const int* in_sizes, int n_in,
                              void* d_out, int out_size) {
    const float* emb = (const float*)d_in[0];
    const int* labels = (const int*)d_in[1];
    float* out = (float*)d_out;

    static bool attr_set = false;
    if (!attr_set) {
        cudaFuncSetAttribute(k_main, cudaFuncAttributeMaxDynamicSharedMemorySize,
                             100 * 1024);
        attr_set = true;
    }

    void* ctl = nullptr;
    cudaGetSymbolAddress(&ctl, g_ctl);
    cudaMemsetAsync(ctl, 0, sizeof(Ctl));

    dim3 grid(4, 4, NSPLIT);
    k_main<<<grid, 256, 96 * 1024>>>(emb, labels, out);
}

// round 5
// speedup vs baseline: 1.5140x; 1.4871x over previous
#include <cuda_runtime.h>
#include <cuda_bf16.h>
#include <cstdint>

#define NB 512
#define ND 512
#define MARGIN 0.2f
#define INF_F 1e30f
#define NSPLIT 8        // K splits of 64
#define KB 64           // K per block

typedef unsigned long long ull;

// ---------------- scratch ----------------
__device__ float g_P[NSPLIT][NB * NB];   // split-K partial dot products (8 MB)

struct Ctl {
    unsigned long long acc;   // fixed-point loss sum (x 2^32)
    unsigned long long cnt;   // valid pair count
    int ready[4];             // per 128-row band: finished blocks (32 = done)
    int diagdone;             // 32 = all diagonal tiles done
    int done;                 // mining blocks finished
};
__device__ Ctl g_ctl;

// ---------------- f32x2 helpers ----------------
__device__ __forceinline__ ull dup2(float x) {
    ull r;
    asm("mov.b64 %0, {%1, %1};" : "=l"(r) : "r"(__float_as_uint(x)));
    return r;
}
__device__ __forceinline__ void fma2(ull& d, ull a, ull b) {
    asm("fma.rn.f32x2 %0, %1, %2, %0;" : "+l"(d) : "l"(a), "l"(b));
}
__device__ __forceinline__ void unpk(ull v, float& lo, float& hi) {
    unsigned l, h;
    asm("mov.b64 {%0, %1}, %2;" : "=r"(l), "=r"(h) : "l"(v));
    lo = __uint_as_float(l);
    hi = __uint_as_float(h);
}

// =====================================================================
// Fused kernel. grid (4,4,8), 256 threads.
//   GEMM 128x128x64 partial -> g_P[bz], conflict-free smem layout.
//   Warp (wr=w>>1, wc=w&1) owns 32x64; lane (ly=lane>>3, lx=lane&7)
//   owns rows wr*32+ly*8..+7, cols wc*64 + {lx*4..+3, 32+lx*4..+3}.
// =====================================================================
__global__ void __launch_bounds__(256, 1)
k_main(const float* __restrict__ E, const int* __restrict__ labels,
       float* __restrict__ out) {
    extern __shared__ float smem[];
    float (*As)[128] = reinterpret_cast<float(*)[128]>(smem);            // 32 KB [k][row]
    float (*Bs)[128] = reinterpret_cast<float(*)[128]>(smem + KB * 128); // 32 KB [k][col]
    __shared__ int s_old;

    const int tid = threadIdx.x;
    const int bj = blockIdx.x, bi = blockIdx.y, bz = blockIdx.z;
    const int lane = tid & 31, warp = tid >> 5;

    // ---------- stage tiles (transposed, conflict-free stores) ----------
    {
        const int r = tid & 127;
        const int half = tid >> 7;                  // 0/1 -> k halves
        const float* Ag = E + (size_t)(bi * 128 + r) * ND + bz * KB;
        const float* Bg = E + (size_t)(bj * 128 + r) * ND + bz * KB;
#pragma unroll
        for (int i = 0; i < 8; i++) {
            const int k = half * 32 + i * 4;
            float4 va = *reinterpret_cast<const float4*>(Ag + k);
            float4 vb = *reinterpret_cast<const float4*>(Bg + k);
            As[k + 0][r] = va.x; As[k + 1][r] = va.y;
            As[k + 2][r] = va.z; As[k + 3][r] = va.w;
            Bs[k + 0][r] = vb.x; Bs[k + 1][r] = vb.y;
            Bs[k + 2][r] = vb.z; Bs[k + 3][r] = vb.w;
        }
    }
    __syncthreads();

    // ---------- compute ----------
    const int wr = warp >> 1;          // 0..3  row warp
    const int wc = warp & 1;           // 0..1  col warp
    const int ly = lane >> 3;          // 0..3
    const int lx = lane & 7;           // 0..7
    const int rbase = wr * 32 + ly * 8;        // 8 rows
    const int cbase = wc * 64 + lx * 4;        // cols cbase..+3 and cbase+32..+35

    ull acc[4][8];                     // [row-pair][col: 0..3 = grp0, 4..7 = grp1]
#pragma unroll
    for (int i = 0; i < 4; i++)
#pragma unroll
        for (int j = 0; j < 8; j++) acc[i][j] = 0ull;

#pragma unroll 4
    for (int kk = 0; kk < KB; kk++) {
        // A: 4 row-pair ulls, broadcast within each 8-lane phase
        ull a0 = *reinterpret_cast<const ull*>(&As[kk][rbase + 0]);
        ull a1 = *reinterpret_cast<const ull*>(&As[kk][rbase + 2]);
        ull a2 = *reinterpret_cast<const ull*>(&As[kk][rbase + 4]);
        ull a3 = *reinterpret_cast<const ull*>(&As[kk][rbase + 6]);
        // B: 2 float4, consecutive addresses per phase -> conflict-free
        float4 bv0 = *reinterpret_cast<const float4*>(&Bs[kk][cbase]);
        float4 bv1 = *reinterpret_cast<const float4*>(&Bs[kk][cbase + 32]);
        ull b[8];
        b[0] = dup2(bv0.x); b[1] = dup2(bv0.y); b[2] = dup2(bv0.z); b[3] = dup2(bv0.w);
        b[4] = dup2(bv1.x); b[5] = dup2(bv1.y); b[6] = dup2(bv1.z); b[7] = dup2(bv1.w);
#pragma unroll
        for (int j = 0; j < 8; j++) {
            fma2(acc[0][j], a0, b[j]);
            fma2(acc[1][j], a1, b[j]);
            fma2(acc[2][j], a2, b[j]);
            fma2(acc[3][j], a3, b[j]);
        }
    }

    // ---------- epilogue: store partial tile ----------
    {
        float* dst = g_P[bz];
#pragma unroll
        for (int rp = 0; rp < 4; rp++) {
            float lo[8], hi[8];
#pragma unroll
            for (int j = 0; j < 8; j++) unpk(acc[rp][j], lo[j], hi[j]);
            const int r0 = bi * 128 + rbase + 2 * rp;
            const int c0 = bj * 128 + cbase;
            float* d0 = &dst[(size_t)r0 * NB + c0];
            float* d1 = &dst[(size_t)(r0 + 1) * NB + c0];
            *reinterpret_cast<float4*>(d0)      = make_float4(lo[0], lo[1], lo[2], lo[3]);
            *reinterpret_cast<float4*>(d0 + 32) = make_float4(lo[4], lo[5], lo[6], lo[7]);
            *reinterpret_cast<float4*>(d1)      = make_float4(hi[0], hi[1], hi[2], hi[3]);
            *reinterpret_cast<float4*>(d1 + 32) = make_float4(hi[4], hi[5], hi[6], hi[7]);
        }
    }

    __threadfence();
    __syncthreads();
    if (tid == 0) {
        if (bi == bj) atomicAdd(&g_ctl.diagdone, 1);
        s_old = atomicAdd(&g_ctl.ready[bi], 1);
    }
    __syncthreads();
    const int old = s_old;
    if (old < 16) return;              // only last 16 finishers per band mine
    const int slice = old - 16;        // 0..15 -> 8 anchors each

    // wait for full band + all diagonal tiles (128 blocks wave-1 resident)
    if (tid == 0) {
        while (*(volatile int*)&g_ctl.ready[bi] < 32 ||
               *(volatile int*)&g_ctl.diagdone < 32) {}
    }
    __syncthreads();
    __threadfence();

    // ---------- mining setup: sq from GEMM diagonal, labels -> smem ----------
    float* s_sq = smem;                    // 512 floats
    int* s_lab = reinterpret_cast<int*>(smem + NB);
    for (int j = tid; j < NB; j += 256) {
        float s = 0.f;
#pragma unroll
        for (int z = 0; z < NSPLIT; z++) s += g_P[z][(size_t)j * NB + j];
        s_sq[j] = s;
        s_lab[j] = labels[j];
    }
    __syncthreads();

    // ---------- mining: warp per anchor ----------
    long long accll = 0, cntll = 0;
    {
        const int a = bi * 128 + slice * 8 + warp;
        const float sqa = s_sq[a];
        const int la = s_lab[a];

        // reg idx = g*4+e  ->  j = g*128 + lane*4 + e
        float d[16];
        int lb[16];
#pragma unroll
        for (int g = 0; g < 4; g++) {
            const int j0 = g * 128 + lane * 4;
            float4 p = make_float4(0.f, 0.f, 0.f, 0.f);
#pragma unroll
            for (int z = 0; z < NSPLIT; z++) {
                float4 v = *reinterpret_cast<const float4*>(&g_P[z][(size_t)a * NB + j0]);
                p.x += v.x; p.y += v.y; p.z += v.z; p.w += v.w;
            }
            float4 sq4 = *reinterpret_cast<const float4*>(&s_sq[j0]);
            int4 lb4 = *reinterpret_cast<const int4*>(&s_lab[j0]);
            d[g * 4 + 0] = fmaxf(sqa + sq4.x - 2.f * p.x, 0.f);
            d[g * 4 + 1] = fmaxf(sqa + sq4.y - 2.f * p.y, 0.f);
            d[g * 4 + 2] = fmaxf(sqa + sq4.z - 2.f * p.z, 0.f);
            d[g * 4 + 3] = fmaxf(sqa + sq4.w - 2.f * p.w, 0.f);
            lb[g * 4 + 0] = lb4.x; lb[g * 4 + 1] = lb4.y;
            lb[g * 4 + 2] = lb4.z; lb[g * 4 + 3] = lb4.w;
        }

        float nmin = INF_F;
#pragma unroll
        for (int t = 0; t < 16; t++)
            if (lb[t] != la) nmin = fminf(nmin, d[t]);
#pragma unroll
        for (int o = 16; o > 0; o >>= 1)
            nmin = fminf(nmin, __shfl_xor_sync(0xFFFFFFFFu, nmin, o));

        float sum = 0.f;
        int cnt = 0;
        if (nmin < 1e29f) {
#pragma unroll 1
            for (int t = 0; t < 16; t++) {
                const int j = (t >> 2) * 128 + lane * 4 + (t & 3);
                unsigned m = __ballot_sync(0xFFFFFFFFu, (j > a) && (lb[t] == la));
                while (m) {
                    const int lp = __ffs(m) - 1;
                    m &= m - 1;
                    const float ap = __shfl_sync(0xFFFFFFFFu, d[t], lp);
                    const float apM = ap + MARGIN;
                    float smin = INF_F;
#pragma unroll
                    for (int tt = 0; tt < 16; tt++) {
                        bool semi = (lb[tt] != la) && (d[tt] > ap) && (d[tt] < apM);
                        if (semi) smin = fminf(smin, d[tt]);
                    }
#pragma unroll
                    for (int o = 16; o > 0; o >>= 1)
                        smin = fminf(smin, __shfl_xor_sync(0xFFFFFFFFu, smin, o));
                    const float negd = (smin < 1e29f) ? smin : nmin;
                    sum += fmaxf(ap - negd + MARGIN, 0.f);
                    cnt++;
                }
            }
        }
        if (lane == 0) {
            accll += __double2ll_rn((double)sum * 4294967296.0);
            cntll += cnt;
        }
    }
    if (lane == 0 && (accll | cntll)) {
        atomicAdd(&g_ctl.acc, (ull)accll);
        atomicAdd(&g_ctl.cnt, (ull)cntll);
    }

    // ---------- finalize ----------
    __syncthreads();
    __threadfence();
    if (tid == 0) {
        const int o = atomicAdd(&g_ctl.done, 1);
        if (o == 63) {
            __threadfence();
            ull a = *(volatile ull*)&g_ctl.acc;
            ull c = *(volatile ull*)&g_ctl.cnt;
            out[0] = (float)(((double)a / 4294967296.0) / (double)(c ? c : 1ull));
        }
    }
}

extern "C" void kernel_launch(void* const* d_in, const int* in_sizes, int n_in,
                              void* d_out, int out_size) {
    const float* emb = (const float*)d_in[0];
    const int* labels = (const int*)d_in[1];
    float* out = (float*)d_out;

    cudaFuncSetAttribute(k_main, cudaFuncAttributeMaxDynamicSharedMemorySize,
                         72 * 1024);

    void* ctl = nullptr;
    cudaGetSymbolAddress(&ctl, g_ctl);
    cudaMemsetAsync(ctl, 0, sizeof(Ctl));

    dim3 grid(4, 4, NSPLIT);
    k_main<<<grid, 256, 64 * 1024>>>(emb, labels, out);
}